// round 1
// baseline (speedup 1.0000x reference)
#include <cuda_runtime.h>
#include <math.h>

#define K_TOP    6000
#define CAND_CAP 8192
#define NMS_CAP  2048

// ---------------- scratch (device globals; no allocations) ----------------
__device__ unsigned long long g_keys[1048576];
__device__ unsigned int       g_hist1[65536];
__device__ unsigned int       g_hist2[65536];
__device__ unsigned int       g_meta[8];   // [0]=t16 [1]=count_above [2]=thresh32 [3]=cand counter
__device__ unsigned long long g_cand[CAND_CAP];
__device__ unsigned long long g_sorted[K_TOP];

// order-preserving float<->uint transform
__device__ __forceinline__ unsigned int f2u(float f) {
    unsigned int b = __float_as_uint(f);
    return b ^ ((b & 0x80000000u) ? 0xFFFFFFFFu : 0x80000000u);
}
__device__ __forceinline__ float u2f(unsigned int u) {
    unsigned int b = (u & 0x80000000u) ? (u ^ 0x80000000u) : ~u;
    return __uint_as_float(b);
}

// ---------------- kernels ----------------
__global__ void k_init() {
    int i = blockIdx.x * blockDim.x + threadIdx.x;
    int stride = gridDim.x * blockDim.x;
    for (int k = i; k < 65536; k += stride) { g_hist1[k] = 0u; g_hist2[k] = 0u; }
    for (int k = i; k < CAND_CAP; k += stride) g_cand[k] = 0ULL;
    if (i < 8) g_meta[i] = 0u;
}

// build composite keys + 16-bit top histogram
__global__ void k_build(const float* __restrict__ probs, int n_scores) {
    int i = blockIdx.x * blockDim.x + threadIdx.x;
    if (i >= n_scores) return;
    int prop = i >> 1, c = i & 1;
    float v = probs[prop * 3 + 1 + c];
    unsigned int u = f2u(v);
    g_keys[i] = ((unsigned long long)u << 32) | (unsigned long long)(0xFFFFFFFFu - (unsigned int)i);
    atomicAdd(&g_hist1[u >> 16], 1u);
}

// find threshold bin (phase 0: top16 bits over g_hist1; phase 1: low16 over g_hist2)
__global__ void k_select(int phase) {
    __shared__ unsigned int s[1024];
    int tid = threadIdx.x;
    const unsigned int* H = (phase == 0) ? g_hist1 : g_hist2;
    unsigned int need = (phase == 0) ? (unsigned int)K_TOP : ((unsigned int)K_TOP - g_meta[1]);
    unsigned int base = tid * 64, cs = 0;
#pragma unroll
    for (int k = 0; k < 64; k++) cs += H[base + k];
    s[tid] = cs; __syncthreads();
    // inclusive suffix sum (Hillis-Steele)
    for (int off = 1; off < 1024; off <<= 1) {
        unsigned int v = (tid + off < 1024) ? s[tid + off] : 0u;
        __syncthreads();
        s[tid] += v;
        __syncthreads();
    }
    unsigned int excl = (tid < 1023) ? s[tid + 1] : 0u;
    if (s[tid] >= need && excl < need) {   // unique crossing chunk
        unsigned int run = excl;
        for (int k = 63; k >= 0; k--) {
            unsigned int h = H[base + k];
            if (run + h >= need) {
                if (phase == 0) { g_meta[0] = base + (unsigned int)k; g_meta[1] = run; }
                else            { g_meta[2] = (g_meta[0] << 16) | (base + (unsigned int)k); }
                break;
            }
            run += h;
        }
    }
}

__global__ void k_hist2(int n_scores) {
    int i = blockIdx.x * blockDim.x + threadIdx.x;
    if (i >= n_scores) return;
    unsigned int u = (unsigned int)(g_keys[i] >> 32);
    if ((u >> 16) == g_meta[0]) atomicAdd(&g_hist2[u & 0xFFFFu], 1u);
}

__global__ void k_compact(int n_scores) {
    int i = blockIdx.x * blockDim.x + threadIdx.x;
    if (i >= n_scores) return;
    unsigned long long key = g_keys[i];
    unsigned int u = (unsigned int)(key >> 32);
    if (u >= g_meta[2]) {
        unsigned int p = atomicAdd(&g_meta[3], 1u);
        if (p < CAND_CAP) g_cand[p] = key;
    }
}

// exact descending order via rank counting (keys are unique; pads are 0)
__global__ void k_rank() {
    __shared__ unsigned long long tile[1024];
    int tid = threadIdx.x;
    int gid = blockIdx.x * 256 + tid;
    unsigned long long my = g_cand[gid];
    int rank = 0;
    for (int base = 0; base < CAND_CAP; base += 1024) {
        for (int k = tid; k < 1024; k += 256) tile[k] = g_cand[base + k];
        __syncthreads();
#pragma unroll 8
        for (int k = 0; k < 1024; k++) rank += (tile[k] > my) ? 1 : 0;
        __syncthreads();
    }
    if (my != 0ULL && rank < K_TOP) g_sorted[rank] = my;
}

// decode top-K, apply box deltas, clip, write detections/class/b
__global__ void k_decode(const float* __restrict__ deltas,
                         const float* __restrict__ anchors,
                         float* __restrict__ out, int n_anchors) {
    int r = blockIdx.x * blockDim.x + threadIdx.x;
    if (r >= K_TOP) return;
    unsigned long long key = g_sorted[r];
    unsigned int u = (unsigned int)(key >> 32);
    unsigned int flat = 0xFFFFFFFFu - (unsigned int)(key & 0xFFFFFFFFu);
    int prop = (int)(flat >> 1);
    int cls = (int)(flat & 1u) + 1;
    float score = u2f(u);
    int b = prop / n_anchors;
    int ai = prop - b * n_anchors;

    const float* a = anchors + (size_t)ai * 4;
    const float* dl = deltas + (size_t)prop * 4;
    float d0 = dl[0] * 0.1f, d1 = dl[1] * 0.1f, d2 = dl[2] * 0.2f, d3 = dl[3] * 0.2f;

    const float inv = 1.0f / 512.0f;
    float ay1 = a[0] * inv, ax1 = a[1] * inv, ay2 = a[2] * inv, ax2 = a[3] * inv;
    float h = ay2 - ay1;
    float w = ax2 - ax1;
    float cy = ay1 + 0.5f * h + d0 * h;
    float cx = ax1 + 0.5f * w + d1 * w;
    h = h * expf(d2);
    w = w * expf(d3);
    float y1 = cy - 0.5f * h;
    float x1 = cx - 0.5f * w;
    float y2 = y1 + h;
    float x2 = x1 + w;
    y1 = fminf(fmaxf(y1 * 512.0f, 0.0f), 512.0f);
    x1 = fminf(fmaxf(x1 * 512.0f, 0.0f), 512.0f);
    y2 = fminf(fmaxf(y2 * 512.0f, 0.0f), 512.0f);
    x2 = fminf(fmaxf(x2 * 512.0f, 0.0f), 512.0f);

    out[r * 6 + 0] = y1;
    out[r * 6 + 1] = x1;
    out[r * 6 + 2] = y2;
    out[r * 6 + 3] = x2;
    out[r * 6 + 4] = score;
    out[r * 6 + 5] = 1.0f;                 // keep (finalized by NMS)
    out[K_TOP * 6 + r] = (float)cls;       // class_ids
    out[K_TOP * 7 + r] = (float)b;         // batch ids
}

// per-(batch,class) greedy NMS; one block per group (16 groups)
__global__ void k_nms(float* __restrict__ out) {
    __shared__ float sy1[NMS_CAP], sx1[NMS_CAP], sy2[NMS_CAP], sx2[NMS_CAP];
    __shared__ int spos[NMS_CAP];
    __shared__ unsigned char skeep[NMS_CAP];
    __shared__ int s_wcnt[8], s_woff[8], s_n;

    int tid = threadIdx.x;
    int bb = blockIdx.x >> 1;
    int cls = (int)(blockIdx.x & 1) + 1;
    float bbf = (float)bb, clsf = (float)cls;

    if (tid == 0) s_n = 0;
    __syncthreads();

    // stable compaction of this group's entries, in global score order
    for (int base = 0; base < K_TOP; base += 256) {
        int r = base + tid;
        bool m = false;
        float y1 = 0.f, x1 = 0.f, y2 = 0.f, x2 = 0.f;
        if (r < K_TOP) {
            float cf = out[K_TOP * 6 + r];
            float bf = out[K_TOP * 7 + r];
            m = (bf == bbf) && (cf == clsf);
            if (m) {
                y1 = out[r * 6 + 0]; x1 = out[r * 6 + 1];
                y2 = out[r * 6 + 2]; x2 = out[r * 6 + 3];
            }
        }
        unsigned int ball = __ballot_sync(0xFFFFFFFFu, m);
        int lane = tid & 31, w = tid >> 5;
        if (lane == 0) s_wcnt[w] = __popc(ball);
        __syncthreads();
        if (tid == 0) {
            int acc = s_n;
            for (int k = 0; k < 8; k++) { s_woff[k] = acc; acc += s_wcnt[k]; }
            s_n = acc;
        }
        __syncthreads();
        if (m) {
            int p = s_woff[w] + __popc(ball & ((1u << lane) - 1u));
            if (p < NMS_CAP) {
                sy1[p] = y1; sx1[p] = x1; sy2[p] = y2; sx2[p] = x2;
                spos[p] = r; skeep[p] = 1;
            }
        }
        __syncthreads();
    }

    int n = min(s_n, NMS_CAP);
    for (int i = 0; i < n; i++) {
        __syncthreads();
        if (!skeep[i]) continue;           // uniform: smem read after sync
        float by1 = sy1[i], bx1 = sx1[i], by2 = sy2[i], bx2 = sx2[i];
        float ba = (by2 - by1 + 1.0f) * (bx2 - bx1 + 1.0f);
        for (int j = i + 1 + tid; j < n; j += 256) {
            if (!skeep[j]) continue;
            float ih = fminf(by2, sy2[j]) - fmaxf(by1, sy1[j]) + 1.0f;
            float iw = fminf(bx2, sx2[j]) - fmaxf(bx1, sx1[j]) + 1.0f;
            ih = fmaxf(ih, 0.0f); iw = fmaxf(iw, 0.0f);
            float inter = ih * iw;
            float aj = (sy2[j] - sy1[j] + 1.0f) * (sx2[j] - sx1[j] + 1.0f);
            float iou = inter / (ba + aj - inter);
            if (iou >= 0.5f) skeep[j] = 0;
        }
    }
    __syncthreads();
    for (int j = tid; j < n; j += 256)
        out[spos[j] * 6 + 5] = skeep[j] ? 1.0f : 0.0f;
}

// ---------------- launch ----------------
extern "C" void kernel_launch(void* const* d_in, const int* in_sizes, int n_in,
                              void* d_out, int out_size) {
    const float* probs   = (const float*)d_in[0];
    const float* deltas  = (const float*)d_in[1];
    const float* anchors = (const float*)d_in[2];
    float* out = (float*)d_out;

    int n_prop    = in_sizes[0] / 3;
    int n_anchors = in_sizes[2] / 4;
    int n_scores  = n_prop * 2;
    int gb = (n_scores + 255) / 256;

    k_init<<<144, 256>>>();
    k_build<<<gb, 256>>>(probs, n_scores);
    k_select<<<1, 1024>>>(0);
    k_hist2<<<gb, 256>>>(n_scores);
    k_select<<<1, 1024>>>(1);
    k_compact<<<gb, 256>>>(n_scores);
    k_rank<<<CAND_CAP / 256, 256>>>();
    k_decode<<<(K_TOP + 255) / 256, 256>>>(deltas, anchors, out, n_anchors);
    k_nms<<<16, 256>>>(out);
}

// round 2
// speedup vs baseline: 3.3089x; 3.3089x over previous
#include <cuda_runtime.h>
#include <math.h>

#define K_TOP    6000
#define CAND_CAP 8192
#define NMS_CAP  1024
#define H1_BINS  4096      // top 12 bits of transformed score
#define H2_BINS  65536     // next 16 bits (bits [4,20))

// ---------------- scratch (device globals; no allocations) ----------------
__device__ unsigned long long g_keys[1048576];
__device__ unsigned int       g_hist1[H1_BINS];
__device__ unsigned int       g_hist2[H2_BINS];
__device__ unsigned int       g_meta[8];   // [0]=t12 [1]=count_above [2]=thresh28 [3]=cand counter
__device__ unsigned long long g_cand[CAND_CAP];
__device__ unsigned long long g_sorted[K_TOP];

// order-preserving float<->uint transform
__device__ __forceinline__ unsigned int f2u(float f) {
    unsigned int b = __float_as_uint(f);
    return b ^ ((b & 0x80000000u) ? 0xFFFFFFFFu : 0x80000000u);
}
__device__ __forceinline__ float u2f(unsigned int u) {
    unsigned int b = (u & 0x80000000u) ? (u ^ 0x80000000u) : ~u;
    return __uint_as_float(b);
}

// ---------------- kernels ----------------
__global__ void k_init() {
    int i = blockIdx.x * blockDim.x + threadIdx.x;
    int stride = gridDim.x * blockDim.x;
    for (int k = i; k < H2_BINS; k += stride) g_hist2[k] = 0u;
    for (int k = i; k < H1_BINS; k += stride) g_hist1[k] = 0u;
    for (int k = i; k < CAND_CAP; k += stride) g_cand[k] = 0ULL;
    if (i < 8) g_meta[i] = 0u;
}

// build composite keys + level-1 (12-bit) histogram in smem, warp-aggregated
__global__ void k_build(const float* __restrict__ probs, int n_scores) {
    __shared__ unsigned int sh[H1_BINS];
    for (int k = threadIdx.x; k < H1_BINS; k += blockDim.x) sh[k] = 0u;
    __syncthreads();

    int stride = gridDim.x * blockDim.x;
    for (int i = blockIdx.x * blockDim.x + threadIdx.x; i < n_scores; i += stride) {
        int prop = i >> 1, c = i & 1;
        float v = probs[prop * 3 + 1 + c];
        unsigned int u = f2u(v);
        g_keys[i] = ((unsigned long long)u << 32) |
                    (unsigned long long)(0xFFFFFFFFu - (unsigned int)i);
        unsigned int bin = u >> 20;
        // warp-aggregate equal bins before the smem atomic
        unsigned int act = __activemask();
        unsigned int peers = __match_any_sync(act, bin);
        int leader = __ffs(peers) - 1;
        if ((threadIdx.x & 31) == leader)
            atomicAdd(&sh[bin], (unsigned int)__popc(peers));
    }
    __syncthreads();
    for (int k = threadIdx.x; k < H1_BINS; k += blockDim.x) {
        unsigned int v = sh[k];
        if (v) atomicAdd(&g_hist1[k], v);
    }
}

// find threshold bin (phase 0: 12-bit over g_hist1; phase 1: 16-bit over g_hist2)
__global__ void k_select(int phase) {
    __shared__ unsigned int s[1024];
    int tid = threadIdx.x;
    const unsigned int* H = (phase == 0) ? g_hist1 : g_hist2;
    int bpt = (phase == 0) ? (H1_BINS / 1024) : (H2_BINS / 1024);
    unsigned int need = (phase == 0) ? (unsigned int)K_TOP
                                     : ((unsigned int)K_TOP - g_meta[1]);
    unsigned int base = tid * bpt, cs = 0;
    for (int k = 0; k < bpt; k++) cs += H[base + k];
    s[tid] = cs; __syncthreads();
    // inclusive suffix sum (Hillis-Steele)
    for (int off = 1; off < 1024; off <<= 1) {
        unsigned int v = (tid + off < 1024) ? s[tid + off] : 0u;
        __syncthreads();
        s[tid] += v;
        __syncthreads();
    }
    unsigned int excl = (tid < 1023) ? s[tid + 1] : 0u;
    if (s[tid] >= need && excl < need) {   // unique crossing chunk
        unsigned int run = excl;
        for (int k = bpt - 1; k >= 0; k--) {
            unsigned int h = H[base + k];
            if (run + h >= need) {
                if (phase == 0) { g_meta[0] = base + (unsigned int)k; g_meta[1] = run; }
                else            { g_meta[2] = (g_meta[0] << 16) | (base + (unsigned int)k); }
                break;
            }
            run += h;
        }
    }
}

__global__ void k_hist2(int n_scores) {
    int i = blockIdx.x * blockDim.x + threadIdx.x;
    if (i >= n_scores) return;
    unsigned int u = (unsigned int)(g_keys[i] >> 32);
    if ((u >> 20) == g_meta[0]) atomicAdd(&g_hist2[(u >> 4) & 0xFFFFu], 1u);
}

__global__ void k_compact(int n_scores) {
    int i = blockIdx.x * blockDim.x + threadIdx.x;
    if (i >= n_scores) return;
    unsigned long long key = g_keys[i];
    unsigned int p28 = (unsigned int)(key >> 36);   // top 28 bits of score part
    if (p28 >= g_meta[2]) {
        unsigned int p = atomicAdd(&g_meta[3], 1u);
        if (p < CAND_CAP) g_cand[p] = key;
    }
}

// exact descending rank via counting; 8 candidates per block, 1024 blocks
#define RC 8
__global__ void k_rank() {
    __shared__ unsigned int partial[RC][8];
    int bc = blockIdx.x * RC;
    unsigned long long cand[RC];
#pragma unroll
    for (int c = 0; c < RC; c++) cand[c] = g_cand[bc + c];
    unsigned int cnt[RC];
#pragma unroll
    for (int c = 0; c < RC; c++) cnt[c] = 0u;

    for (int j = threadIdx.x; j < CAND_CAP; j += 256) {
        unsigned long long k = g_cand[j];
#pragma unroll
        for (int c = 0; c < RC; c++) cnt[c] += (k > cand[c]) ? 1u : 0u;
    }
    int lane = threadIdx.x & 31, w = threadIdx.x >> 5;
#pragma unroll
    for (int c = 0; c < RC; c++) {
#pragma unroll
        for (int off = 16; off > 0; off >>= 1)
            cnt[c] += __shfl_down_sync(0xFFFFFFFFu, cnt[c], off);
        if (lane == 0) partial[c][w] = cnt[c];
    }
    __syncthreads();
    if (threadIdx.x < RC) {
        int c = threadIdx.x;
        unsigned int rank = 0;
#pragma unroll
        for (int k = 0; k < 8; k++) rank += partial[c][k];
        unsigned long long my = cand[c];
        if (my != 0ULL && rank < K_TOP) g_sorted[rank] = my;
    }
}

// decode top-K, apply box deltas, clip, write detections/class/b
__global__ void k_decode(const float* __restrict__ deltas,
                         const float* __restrict__ anchors,
                         float* __restrict__ out, int n_anchors) {
    int r = blockIdx.x * blockDim.x + threadIdx.x;
    if (r >= K_TOP) return;
    unsigned long long key = g_sorted[r];
    unsigned int u = (unsigned int)(key >> 32);
    unsigned int flat = 0xFFFFFFFFu - (unsigned int)(key & 0xFFFFFFFFu);
    int prop = (int)(flat >> 1);
    int cls = (int)(flat & 1u) + 1;
    float score = u2f(u);
    int b = prop / n_anchors;
    int ai = prop - b * n_anchors;

    const float* a = anchors + (size_t)ai * 4;
    const float* dl = deltas + (size_t)prop * 4;
    float d0 = dl[0] * 0.1f, d1 = dl[1] * 0.1f, d2 = dl[2] * 0.2f, d3 = dl[3] * 0.2f;

    const float inv = 1.0f / 512.0f;
    float ay1 = a[0] * inv, ax1 = a[1] * inv, ay2 = a[2] * inv, ax2 = a[3] * inv;
    float h = ay2 - ay1;
    float w = ax2 - ax1;
    float cy = ay1 + 0.5f * h + d0 * h;
    float cx = ax1 + 0.5f * w + d1 * w;
    h = h * expf(d2);
    w = w * expf(d3);
    float y1 = cy - 0.5f * h;
    float x1 = cx - 0.5f * w;
    float y2 = y1 + h;
    float x2 = x1 + w;
    y1 = fminf(fmaxf(y1 * 512.0f, 0.0f), 512.0f);
    x1 = fminf(fmaxf(x1 * 512.0f, 0.0f), 512.0f);
    y2 = fminf(fmaxf(y2 * 512.0f, 0.0f), 512.0f);
    x2 = fminf(fmaxf(x2 * 512.0f, 0.0f), 512.0f);

    out[r * 6 + 0] = y1;
    out[r * 6 + 1] = x1;
    out[r * 6 + 2] = y2;
    out[r * 6 + 3] = x2;
    out[r * 6 + 4] = score;
    out[r * 6 + 5] = 1.0f;                 // keep (finalized by NMS)
    out[K_TOP * 6 + r] = (float)cls;       // class_ids
    out[K_TOP * 7 + r] = (float)b;         // batch ids
}

// per-(batch,class) mask-based NMS; one block per group (16 groups)
// dynamic smem layout: by1|bx1|by2|bx2 (f32 x NMS_CAP each), spos (i32 x NMS_CAP),
//                      mask (u32 x NMS_CAP x 32)
__global__ void k_nms(float* __restrict__ out) {
    extern __shared__ unsigned char dyn[];
    float* sy1 = (float*)dyn;
    float* sx1 = sy1 + NMS_CAP;
    float* sy2 = sx1 + NMS_CAP;
    float* sx2 = sy2 + NMS_CAP;
    int* spos  = (int*)(sx2 + NMS_CAP);
    unsigned int* mask = (unsigned int*)(spos + NMS_CAP);   // [NMS_CAP][32]

    __shared__ int s_wcnt[8], s_woff[8], s_n;
    __shared__ unsigned int s_remv[32];

    int tid = threadIdx.x;
    int bb = blockIdx.x >> 1;
    int cls = (int)(blockIdx.x & 1) + 1;
    float bbf = (float)bb, clsf = (float)cls;

    if (tid == 0) s_n = 0;
    __syncthreads();

    // stable compaction of this group's entries, in global score order
    for (int base = 0; base < K_TOP; base += 256) {
        int r = base + tid;
        bool m = false;
        float y1 = 0.f, x1 = 0.f, y2 = 0.f, x2 = 0.f;
        if (r < K_TOP) {
            float cf = out[K_TOP * 6 + r];
            float bf = out[K_TOP * 7 + r];
            m = (bf == bbf) && (cf == clsf);
            if (m) {
                y1 = out[r * 6 + 0]; x1 = out[r * 6 + 1];
                y2 = out[r * 6 + 2]; x2 = out[r * 6 + 3];
            }
        }
        unsigned int ball = __ballot_sync(0xFFFFFFFFu, m);
        int lane = tid & 31, w = tid >> 5;
        if (lane == 0) s_wcnt[w] = __popc(ball);
        __syncthreads();
        if (tid == 0) {
            int acc = s_n;
            for (int k = 0; k < 8; k++) { s_woff[k] = acc; acc += s_wcnt[k]; }
            s_n = acc;
        }
        __syncthreads();
        if (m) {
            int p = s_woff[w] + __popc(ball & ((1u << lane) - 1u));
            if (p < NMS_CAP) {
                sy1[p] = y1; sx1[p] = x1; sy2[p] = y2; sx2[p] = x2;
                spos[p] = r;
            }
        }
        __syncthreads();
    }

    int n = min(s_n, NMS_CAP);

    // parallel suppression-mask build: bit j of mask[i][*] set if i suppresses j (j>i)
    for (int i = tid; i < n; i += 256) {
        float iy1 = sy1[i], ix1 = sx1[i], iy2 = sy2[i], ix2 = sx2[i];
        float ia = (iy2 - iy1 + 1.0f) * (ix2 - ix1 + 1.0f);
        for (int w = 0; w < 32; w++) {
            int jbase = w * 32;
            if (jbase >= n) { mask[i * 32 + w] = 0u; continue; }
            unsigned int mw = 0u;
#pragma unroll 4
            for (int bit = 0; bit < 32; bit++) {
                int j = jbase + bit;
                if (j > i && j < n) {
                    float ih = fminf(iy2, sy2[j]) - fmaxf(iy1, sy1[j]) + 1.0f;
                    float iw = fminf(ix2, sx2[j]) - fmaxf(ix1, sx1[j]) + 1.0f;
                    ih = fmaxf(ih, 0.0f); iw = fmaxf(iw, 0.0f);
                    float inter = ih * iw;
                    float ja = (sy2[j] - sy1[j] + 1.0f) * (sx2[j] - sx1[j] + 1.0f);
                    if (inter >= 0.5f * (ia + ja - inter)) mw |= (1u << bit);
                }
            }
            mask[i * 32 + w] = mw;
        }
    }
    __syncthreads();

    // sequential bit-reduce by warp 0; lane l owns removal word l
    if (tid < 32) {
        unsigned int remv = 0u;
        for (int i = 0; i < n; i++) {
            unsigned int wv = __shfl_sync(0xFFFFFFFFu, remv, i >> 5);
            if (!((wv >> (i & 31)) & 1u))
                remv |= mask[i * 32 + tid];
        }
        s_remv[tid] = remv;
    }
    __syncthreads();

    for (int j = tid; j < n; j += 256)
        out[spos[j] * 6 + 5] = ((s_remv[j >> 5] >> (j & 31)) & 1u) ? 0.0f : 1.0f;
}

// ---------------- launch ----------------
extern "C" void kernel_launch(void* const* d_in, const int* in_sizes, int n_in,
                              void* d_out, int out_size) {
    const float* probs   = (const float*)d_in[0];
    const float* deltas  = (const float*)d_in[1];
    const float* anchors = (const float*)d_in[2];
    float* out = (float*)d_out;

    int n_prop    = in_sizes[0] / 3;
    int n_anchors = in_sizes[2] / 4;
    int n_scores  = n_prop * 2;
    int gb = (n_scores + 255) / 256;

    const int nms_smem = NMS_CAP * (4 * 4 + 4 + 32 * 4);   // 151552 bytes
    cudaFuncSetAttribute(k_nms, cudaFuncAttributeMaxDynamicSharedMemorySize, nms_smem);

    k_init<<<128, 256>>>();
    k_build<<<296, 256>>>(probs, n_scores);
    k_select<<<1, 1024>>>(0);
    k_hist2<<<gb, 256>>>(n_scores);
    k_select<<<1, 1024>>>(1);
    k_compact<<<gb, 256>>>(n_scores);
    k_rank<<<CAND_CAP / RC, 256>>>();
    k_decode<<<(K_TOP + 255) / 256, 256>>>(deltas, anchors, out, n_anchors);
    k_nms<<<16, 256, nms_smem>>>(out);
}

// round 3
// speedup vs baseline: 4.0722x; 1.2307x over previous
#include <cuda_runtime.h>
#include <math.h>

#define K_TOP    6000
#define CAND_CAP 16384
#define NMS_CAP  1024
#define HBINS    4096      // top 12 bits of transformed score
#define RC       8

// ---------------- scratch (device globals; no allocations) ----------------
__device__ unsigned int       g_hist[HBINS];
__device__ unsigned int       g_meta[8];     // [3] = candidate counter
__device__ unsigned long long g_cand[CAND_CAP];

// order-preserving float<->uint transform
__device__ __forceinline__ unsigned int f2u(float f) {
    unsigned int b = __float_as_uint(f);
    return b ^ ((b & 0x80000000u) ? 0xFFFFFFFFu : 0x80000000u);
}
__device__ __forceinline__ float u2f(unsigned int u) {
    unsigned int b = (u & 0x80000000u) ? (u ^ 0x80000000u) : ~u;
    return __uint_as_float(b);
}

// ---------------- kernel 1: 12-bit histogram of fg scores ----------------
__global__ void k_hist(const float* __restrict__ probs, int n_groups) {
    __shared__ unsigned int sh[HBINS];
    for (int k = threadIdx.x; k < HBINS; k += blockDim.x) sh[k] = 0u;
    __syncthreads();

    const float4* __restrict__ p4 = (const float4*)probs;
    int stride = gridDim.x * blockDim.x;
    for (int g = blockIdx.x * blockDim.x + threadIdx.x; g < n_groups; g += stride) {
        float4 A = p4[g * 3 + 0], B = p4[g * 3 + 1], C = p4[g * 3 + 2];
        float s[8] = {A.y, A.z, B.x, B.y, B.w, C.x, C.z, C.w};
#pragma unroll
        for (int k = 0; k < 8; k++) {
            unsigned int bin = f2u(s[k]) >> 20;
            unsigned int act = __activemask();
            unsigned int peers = __match_any_sync(act, bin);
            int leader = __ffs(peers) - 1;
            if ((threadIdx.x & 31) == leader)
                atomicAdd(&sh[bin], (unsigned int)__popc(peers));
        }
    }
    __syncthreads();
    for (int k = threadIdx.x; k < HBINS; k += blockDim.x) {
        unsigned int v = sh[k];
        if (v) atomicAdd(&g_hist[k], v);
    }
}

// ------- kernel 2: per-block threshold prologue + candidate collection -------
__global__ void k_collect(const float* __restrict__ probs, int n_groups) {
    __shared__ unsigned int ssum[256];
    __shared__ unsigned int s_t;
    int tid = threadIdx.x;
    int lane = tid & 31;

    // threshold bin from g_hist (each block computes it independently; L2-hot)
    unsigned int cs = 0;
    int base = tid * (HBINS / 256);
#pragma unroll
    for (int k = 0; k < HBINS / 256; k++) cs += g_hist[base + k];
    ssum[tid] = cs; __syncthreads();
    for (int off = 1; off < 256; off <<= 1) {      // inclusive suffix sum
        unsigned int v = (tid + off < 256) ? ssum[tid + off] : 0u;
        __syncthreads();
        ssum[tid] += v;
        __syncthreads();
    }
    unsigned int excl = (tid < 255) ? ssum[tid + 1] : 0u;
    if (ssum[tid] >= (unsigned)K_TOP && excl < (unsigned)K_TOP) {   // unique crossing
        unsigned int run = excl;
        for (int k = HBINS / 256 - 1; k >= 0; k--) {
            run += g_hist[base + k];
            if (run >= (unsigned)K_TOP) { s_t = (unsigned int)(base + k); break; }
        }
    }
    __syncthreads();
    unsigned int t = s_t;

    const float4* __restrict__ p4 = (const float4*)probs;
    int stride = gridDim.x * blockDim.x;
    for (int g = blockIdx.x * blockDim.x + tid; g < n_groups; g += stride) {
        float4 A = p4[g * 3 + 0], B = p4[g * 3 + 1], C = p4[g * 3 + 2];
        float s[8] = {A.y, A.z, B.x, B.y, B.w, C.x, C.z, C.w};
#pragma unroll
        for (int k = 0; k < 8; k++) {
            unsigned int u = f2u(s[k]);
            bool e = (u >> 20) >= t;
            unsigned int act = __activemask();
            unsigned int ball = __ballot_sync(act, e);
            if (ball) {
                int leader = __ffs(ball) - 1;
                unsigned int posb = 0;
                if (lane == leader)
                    posb = atomicAdd(&g_meta[3], (unsigned int)__popc(ball));
                posb = __shfl_sync(act, posb, leader);
                if (e) {
                    unsigned int my = posb + __popc(ball & ((1u << lane) - 1u));
                    if (my < CAND_CAP) {
                        unsigned int flat = (unsigned int)((g * 4 + (k >> 1)) * 2 + (k & 1));
                        g_cand[my] = ((unsigned long long)u << 32) |
                                     (unsigned long long)(0xFFFFFFFFu - flat);
                    }
                }
            }
        }
    }
}

// ------- kernel 3: exact rank by counting + fused decode/write -------
__global__ void k_rankdec(const float* __restrict__ deltas,
                          const float* __restrict__ anchors,
                          float* __restrict__ out, int n_anchors) {
    __shared__ unsigned int partial[RC][8];
    int m = (int)min(g_meta[3], (unsigned int)CAND_CAP);
    int bc = blockIdx.x * RC;
    if (bc >= m) return;

    unsigned long long cand[RC];
#pragma unroll
    for (int c = 0; c < RC; c++)
        cand[c] = (bc + c < m) ? g_cand[bc + c] : 0xFFFFFFFFFFFFFFFFULL;
    unsigned int cnt[RC];
#pragma unroll
    for (int c = 0; c < RC; c++) cnt[c] = 0u;

    for (int j = threadIdx.x; j < m; j += 256) {
        unsigned long long k = g_cand[j];
#pragma unroll
        for (int c = 0; c < RC; c++) cnt[c] += (k > cand[c]) ? 1u : 0u;
    }
    int lane = threadIdx.x & 31, w = threadIdx.x >> 5;
#pragma unroll
    for (int c = 0; c < RC; c++) {
#pragma unroll
        for (int off = 16; off > 0; off >>= 1)
            cnt[c] += __shfl_down_sync(0xFFFFFFFFu, cnt[c], off);
        if (lane == 0) partial[c][w] = cnt[c];
    }
    __syncthreads();

    if (threadIdx.x < RC) {
        int c = threadIdx.x;
        if (bc + c < m) {
            unsigned int rank = 0;
#pragma unroll
            for (int k = 0; k < 8; k++) rank += partial[c][k];
            if (rank < K_TOP) {
                int r = (int)rank;
                unsigned long long key = cand[c];
                unsigned int u = (unsigned int)(key >> 32);
                unsigned int flat = 0xFFFFFFFFu - (unsigned int)(key & 0xFFFFFFFFu);
                int prop = (int)(flat >> 1);
                int cls = (int)(flat & 1u) + 1;
                float score = u2f(u);
                int b = prop / n_anchors;
                int ai = prop - b * n_anchors;

                const float* a  = anchors + (size_t)ai * 4;
                const float* dl = deltas + (size_t)prop * 4;
                float d0 = dl[0] * 0.1f, d1 = dl[1] * 0.1f;
                float d2 = dl[2] * 0.2f, d3 = dl[3] * 0.2f;

                const float inv = 1.0f / 512.0f;
                float ay1 = a[0] * inv, ax1 = a[1] * inv;
                float ay2 = a[2] * inv, ax2 = a[3] * inv;
                float h = ay2 - ay1;
                float w2 = ax2 - ax1;
                float cy = ay1 + 0.5f * h + d0 * h;
                float cx = ax1 + 0.5f * w2 + d1 * w2;
                h = h * expf(d2);
                w2 = w2 * expf(d3);
                float y1 = cy - 0.5f * h;
                float x1 = cx - 0.5f * w2;
                float y2 = y1 + h;
                float x2 = x1 + w2;
                y1 = fminf(fmaxf(y1 * 512.0f, 0.0f), 512.0f);
                x1 = fminf(fmaxf(x1 * 512.0f, 0.0f), 512.0f);
                y2 = fminf(fmaxf(y2 * 512.0f, 0.0f), 512.0f);
                x2 = fminf(fmaxf(x2 * 512.0f, 0.0f), 512.0f);

                out[r * 6 + 0] = y1;
                out[r * 6 + 1] = x1;
                out[r * 6 + 2] = y2;
                out[r * 6 + 3] = x2;
                out[r * 6 + 4] = score;
                out[r * 6 + 5] = 1.0f;                 // keep (finalized by NMS)
                out[K_TOP * 6 + r] = (float)cls;       // class_ids
                out[K_TOP * 7 + r] = (float)b;         // batch ids
            }
        }
    }
}

// ------- kernel 4: per-(batch,class) mask-based NMS + scratch cleanup -------
// dynamic smem: by1|bx1|by2|bx2 (f32 x NMS_CAP), spos (i32 x NMS_CAP),
//               mask (u32 x NMS_CAP x 32)
__global__ void k_nms(float* __restrict__ out) {
    extern __shared__ unsigned char dyn[];
    float* sy1 = (float*)dyn;
    float* sx1 = sy1 + NMS_CAP;
    float* sy2 = sx1 + NMS_CAP;
    float* sx2 = sy2 + NMS_CAP;
    int* spos  = (int*)(sx2 + NMS_CAP);
    unsigned int* mask = (unsigned int*)(spos + NMS_CAP);   // [NMS_CAP][32]

    __shared__ int s_wcnt[8], s_woff[8], s_n;
    __shared__ unsigned int s_remv[32];

    int tid = threadIdx.x;

    // cleanup scratch for next graph replay (16 blocks x 256 threads = 4096 bins)
    g_hist[blockIdx.x * (HBINS / 16) + tid] = 0u;
    if (blockIdx.x == 0 && tid == 0) g_meta[3] = 0u;

    int bb = blockIdx.x >> 1;
    int cls = (int)(blockIdx.x & 1) + 1;
    float bbf = (float)bb, clsf = (float)cls;

    if (tid == 0) s_n = 0;
    __syncthreads();

    // stable compaction of this group's entries, in global score order
    for (int base = 0; base < K_TOP; base += 256) {
        int r = base + tid;
        bool m = false;
        float y1 = 0.f, x1 = 0.f, y2 = 0.f, x2 = 0.f;
        if (r < K_TOP) {
            float cf = out[K_TOP * 6 + r];
            float bf = out[K_TOP * 7 + r];
            m = (bf == bbf) && (cf == clsf);
            if (m) {
                y1 = out[r * 6 + 0]; x1 = out[r * 6 + 1];
                y2 = out[r * 6 + 2]; x2 = out[r * 6 + 3];
            }
        }
        unsigned int ball = __ballot_sync(0xFFFFFFFFu, m);
        int lane = tid & 31, w = tid >> 5;
        if (lane == 0) s_wcnt[w] = __popc(ball);
        __syncthreads();
        if (tid == 0) {
            int acc = s_n;
            for (int k = 0; k < 8; k++) { s_woff[k] = acc; acc += s_wcnt[k]; }
            s_n = acc;
        }
        __syncthreads();
        if (m) {
            int p = s_woff[w] + __popc(ball & ((1u << lane) - 1u));
            if (p < NMS_CAP) {
                sy1[p] = y1; sx1[p] = x1; sy2[p] = y2; sx2[p] = x2;
                spos[p] = r;
            }
        }
        __syncthreads();
    }

    int n = min(s_n, NMS_CAP);

    // parallel suppression-mask build: bit j of mask[i][*] set if i suppresses j (j>i)
    for (int i = tid; i < n; i += 256) {
        float iy1 = sy1[i], ix1 = sx1[i], iy2 = sy2[i], ix2 = sx2[i];
        float ia = (iy2 - iy1 + 1.0f) * (ix2 - ix1 + 1.0f);
        for (int w = 0; w < 32; w++) {
            int jbase = w * 32;
            if (jbase >= n) { mask[i * 32 + w] = 0u; continue; }
            unsigned int mw = 0u;
#pragma unroll 4
            for (int bit = 0; bit < 32; bit++) {
                int j = jbase + bit;
                if (j > i && j < n) {
                    float ih = fminf(iy2, sy2[j]) - fmaxf(iy1, sy1[j]) + 1.0f;
                    float iw = fminf(ix2, sx2[j]) - fmaxf(ix1, sx1[j]) + 1.0f;
                    ih = fmaxf(ih, 0.0f); iw = fmaxf(iw, 0.0f);
                    float inter = ih * iw;
                    float ja = (sy2[j] - sy1[j] + 1.0f) * (sx2[j] - sx1[j] + 1.0f);
                    if (inter >= 0.5f * (ia + ja - inter)) mw |= (1u << bit);
                }
            }
            mask[i * 32 + w] = mw;
        }
    }
    __syncthreads();

    // sequential bit-reduce by warp 0; lane l owns removal word l
    if (tid < 32) {
        unsigned int remv = 0u;
        for (int i = 0; i < n; i++) {
            unsigned int wv = __shfl_sync(0xFFFFFFFFu, remv, i >> 5);
            if (!((wv >> (i & 31)) & 1u))
                remv |= mask[i * 32 + tid];
        }
        s_remv[tid] = remv;
    }
    __syncthreads();

    for (int j = tid; j < n; j += 256)
        out[spos[j] * 6 + 5] = ((s_remv[j >> 5] >> (j & 31)) & 1u) ? 0.0f : 1.0f;
}

// ---------------- launch ----------------
extern "C" void kernel_launch(void* const* d_in, const int* in_sizes, int n_in,
                              void* d_out, int out_size) {
    const float* probs   = (const float*)d_in[0];
    const float* deltas  = (const float*)d_in[1];
    const float* anchors = (const float*)d_in[2];
    float* out = (float*)d_out;

    int n_prop    = in_sizes[0] / 3;
    int n_anchors = in_sizes[2] / 4;
    int n_groups  = n_prop / 4;          // 4 props (12 floats = 3 float4) per thread-step

    const int nms_smem = NMS_CAP * (4 * 4 + 4 + 32 * 4);   // 151552 bytes
    cudaFuncSetAttribute(k_nms, cudaFuncAttributeMaxDynamicSharedMemorySize, nms_smem);

    k_hist<<<148, 512>>>(probs, n_groups);
    k_collect<<<296, 256>>>(probs, n_groups);
    k_rankdec<<<CAND_CAP / RC, 256>>>(deltas, anchors, out, n_anchors);
    k_nms<<<16, 256, nms_smem>>>(out);
}